// round 6
// baseline (speedup 1.0000x reference)
#include <cuda_runtime.h>
#include <math.h>

// Problem constants
#define NN        512
#define ROWS      256
#define BM        32
#define BN        32
#define BK        32
#define NB_GEMM   128          // 8 row tiles * 16 n tiles
#define THREADS   256

#define SAMPLE_ELEMS 131072
#define STD_BYTES    268435456ull   // 256*512*512 floats * 4B

// Scratch for the softplus diagonal values (512 KB static device array)
__device__ float g_diag[SAMPLE_ELEMS];

__global__ __launch_bounds__(THREADS)
void gaussian_sampler_gemm(const float* __restrict__ x,
                           const float* __restrict__ W,
                           const float* __restrict__ b,
                           const float* __restrict__ eps,
                           float* __restrict__ out)
{
    float* __restrict__ outS = out;                       // sample
    float* __restrict__ outM = out + SAMPLE_ELEMS;        // mu

    __shared__ float Xs[BM][BK + 1];
    __shared__ float Wv[BN][BK + 1];
    __shared__ float Wm[BN][BK + 1];

    const int bm   = blockIdx.x >> 4;
    const int bn   = blockIdx.x & 15;
    const int row0 = bm * BM;
    const int n0   = bn * BN;

    const int tid = threadIdx.x;
    const int tx  = tid & 15;
    const int ty  = tid >> 4;
    const int rl  = ty * 2;
    const int nl  = tx * 2;

    const int lr = tid >> 3;
    const int lc = (tid & 7) * 4;

    float av[2][2] = {{0.f,0.f},{0.f,0.f}};
    float am[2][2] = {{0.f,0.f},{0.f,0.f}};

    for (int k0 = 0; k0 < NN; k0 += BK) {
        float4 xv = *reinterpret_cast<const float4*>(&x[(size_t)(row0 + lr) * NN + k0 + lc]);
        Xs[lr][lc + 0] = xv.x; Xs[lr][lc + 1] = xv.y;
        Xs[lr][lc + 2] = xv.z; Xs[lr][lc + 3] = xv.w;

        float4 wv = *reinterpret_cast<const float4*>(&W[(size_t)(n0 + lr) * NN + k0 + lc]);
        Wv[lr][lc + 0] = wv.x; Wv[lr][lc + 1] = wv.y;
        Wv[lr][lc + 2] = wv.z; Wv[lr][lc + 3] = wv.w;

        float4 wm = *reinterpret_cast<const float4*>(&W[(size_t)(512 + n0 + lr) * NN + k0 + lc]);
        Wm[lr][lc + 0] = wm.x; Wm[lr][lc + 1] = wm.y;
        Wm[lr][lc + 2] = wm.z; Wm[lr][lc + 3] = wm.w;

        __syncthreads();

        #pragma unroll
        for (int kk = 0; kk < BK; kk++) {
            float x0 = Xs[rl][kk],     x1 = Xs[rl + 1][kk];
            float v0 = Wv[nl][kk],     v1 = Wv[nl + 1][kk];
            float m0 = Wm[nl][kk],     m1 = Wm[nl + 1][kk];
            av[0][0] += x0 * v0;  av[0][1] += x0 * v1;
            av[1][0] += x1 * v0;  av[1][1] += x1 * v1;
            am[0][0] += x0 * m0;  am[0][1] += x0 * m1;
            am[1][0] += x1 * m0;  am[1][1] += x1 * m1;
        }
        __syncthreads();
    }

    #pragma unroll
    for (int rr = 0; rr < 2; rr++) {
        #pragma unroll
        for (int nn = 0; nn < 2; nn++) {
            const int row = row0 + rl + rr;
            const int n   = n0 + nl + nn;
            float v  = av[rr][nn] + b[n];
            float m  = am[rr][nn] + b[512 + n];
            float sp = (v > 20.f) ? v : log1pf(expf(v));   // softplus, overflow-safe
            const int idx = row * NN + n;
            outM[idx] = m;
            outS[idx] = m + sqrtf(sp) * eps[idx];
            g_diag[idx] = sp;                              // stash diagonal (std_mat untouched)
        }
    }
}

// Scatter the softplus diagonal over the zeroed std_mat (after memset joins)
__global__ __launch_bounds__(THREADS)
void diag_fixup(float* __restrict__ out)
{
    float* __restrict__ outD = out + 2 * SAMPLE_ELEMS;
    const unsigned i = blockIdx.x * THREADS + threadIdx.x;   // 0..131071
    outD[(size_t)i * NN + (i & 511u)] = g_diag[i];
}

extern "C" void kernel_launch(void* const* d_in, const int* in_sizes, int n_in,
                              void* d_out, int out_size)
{
    const float* x   = (const float*)d_in[0];   // (2,128,512)
    const float* W   = (const float*)d_in[1];   // (1024,512)
    const float* b   = (const float*)d_in[2];   // (1024,)
    const float* eps = (const float*)d_in[3];   // (2,128,512)
    float* out = (float*)d_out;

    (void)in_sizes; (void)n_in; (void)out_size;

    // One-time resources, created on the first (correctness) call — before graph capture.
    static cudaStream_t s_side = nullptr;
    static cudaEvent_t  e_fork = nullptr;
    static cudaEvent_t  e_join = nullptr;
    if (s_side == nullptr) {
        cudaStreamCreateWithFlags(&s_side, cudaStreamNonBlocking);
        cudaEventCreateWithFlags(&e_fork, cudaEventDisableTiming);
        cudaEventCreateWithFlags(&e_join, cudaEventDisableTiming);
    }

    // Fork: side stream zeroes std_mat (driver-optimized memset, ~6.1 TB/s)
    cudaEventRecord(e_fork, 0);
    cudaStreamWaitEvent(s_side, e_fork, 0);
    cudaMemsetAsync(out + 2 * SAMPLE_ELEMS, 0, STD_BYTES, s_side);

    // Concurrently on origin stream: GEMM (sample, mu, diag scratch)
    gaussian_sampler_gemm<<<NB_GEMM, THREADS>>>(x, W, b, eps, out);

    // Join: fixup waits for BOTH the memset (event) and the GEMM (stream order)
    cudaEventRecord(e_join, s_side);
    cudaStreamWaitEvent(0, e_join, 0);
    diag_fixup<<<SAMPLE_ELEMS / THREADS, THREADS>>>(out);
}

// round 7
// speedup vs baseline: 2.0020x; 2.0020x over previous
#include <cuda_runtime.h>
#include <math.h>

// Problem constants
#define NN        512
#define ROWS      256
#define BM        32
#define BN        32           // n-cols per tile (each n -> var col n and mu col n+512)
#define BK        32
#define NTILES    128          // (ROWS/BM)*(NN/BN) = 8*16
#define KSPLIT    4
#define KCHUNK    128          // 512 / KSPLIT
#define THREADS   256

#define SAMPLE_ELEMS 131072
#define STD_BYTES    268435456ull   // 256*512*512 floats * 4B

// Split-K partial sums: [chunk][row][n]  (2 MB each)
__device__ float g_pv[KSPLIT][ROWS][NN];
__device__ float g_pm[KSPLIT][ROWS][NN];

__global__ __launch_bounds__(THREADS)
void gemm_stage1(const float* __restrict__ x,
                 const float* __restrict__ W)
{
    __shared__ float Xs[BM][BK + 1];
    __shared__ float Wv[BN][BK + 1];
    __shared__ float Wm[BN][BK + 1];

    const int tile  = blockIdx.x & 127;    // 0..127
    const int chunk = blockIdx.x >> 7;     // 0..3
    const int bm    = tile >> 4;
    const int bn    = tile & 15;
    const int row0  = bm * BM;
    const int n0    = bn * BN;
    const int kbeg  = chunk * KCHUNK;

    const int tid = threadIdx.x;
    const int tx  = tid & 15;
    const int ty  = tid >> 4;
    const int rl  = ty * 2;
    const int nl  = tx * 2;

    const int lr = tid >> 3;               // staging row 0..31
    const int lc = (tid & 7) * 4;          // staging float4 col

    float av[2][2] = {{0.f,0.f},{0.f,0.f}};
    float am[2][2] = {{0.f,0.f},{0.f,0.f}};

    for (int k0 = kbeg; k0 < kbeg + KCHUNK; k0 += BK) {
        float4 xv = *reinterpret_cast<const float4*>(&x[(size_t)(row0 + lr) * NN + k0 + lc]);
        Xs[lr][lc + 0] = xv.x; Xs[lr][lc + 1] = xv.y;
        Xs[lr][lc + 2] = xv.z; Xs[lr][lc + 3] = xv.w;

        float4 wv = *reinterpret_cast<const float4*>(&W[(size_t)(n0 + lr) * NN + k0 + lc]);
        Wv[lr][lc + 0] = wv.x; Wv[lr][lc + 1] = wv.y;
        Wv[lr][lc + 2] = wv.z; Wv[lr][lc + 3] = wv.w;

        float4 wm = *reinterpret_cast<const float4*>(&W[(size_t)(512 + n0 + lr) * NN + k0 + lc]);
        Wm[lr][lc + 0] = wm.x; Wm[lr][lc + 1] = wm.y;
        Wm[lr][lc + 2] = wm.z; Wm[lr][lc + 3] = wm.w;

        __syncthreads();

        #pragma unroll
        for (int kk = 0; kk < BK; kk++) {
            float x0 = Xs[rl][kk],     x1 = Xs[rl + 1][kk];
            float v0 = Wv[nl][kk],     v1 = Wv[nl + 1][kk];
            float m0 = Wm[nl][kk],     m1 = Wm[nl + 1][kk];
            av[0][0] += x0 * v0;  av[0][1] += x0 * v1;
            av[1][0] += x1 * v0;  av[1][1] += x1 * v1;
            am[0][0] += x0 * m0;  am[0][1] += x0 * m1;
            am[1][0] += x1 * m0;  am[1][1] += x1 * m1;
        }
        __syncthreads();
    }

    #pragma unroll
    for (int rr = 0; rr < 2; rr++) {
        #pragma unroll
        for (int nn = 0; nn < 2; nn++) {
            g_pv[chunk][row0 + rl + rr][n0 + nl + nn] = av[rr][nn];
            g_pm[chunk][row0 + rl + rr][n0 + nl + nn] = am[rr][nn];
        }
    }
}

// Combine partials (fixed order -> deterministic), write sample, mu, diag of std_mat
__global__ __launch_bounds__(THREADS)
void combine_stage2(const float* __restrict__ b,
                    const float* __restrict__ eps,
                    float* __restrict__ out)
{
    float* __restrict__ outS = out;
    float* __restrict__ outM = out + SAMPLE_ELEMS;
    float* __restrict__ outD = out + 2 * SAMPLE_ELEMS;

    const unsigned i = blockIdx.x * THREADS + threadIdx.x;   // 0..131071
    const unsigned r = i >> 9;
    const unsigned n = i & 511u;

    float v = ((g_pv[0][r][n] + g_pv[1][r][n]) + (g_pv[2][r][n] + g_pv[3][r][n])) + b[n];
    float m = ((g_pm[0][r][n] + g_pm[1][r][n]) + (g_pm[2][r][n] + g_pm[3][r][n])) + b[512 + n];
    float sp = (v > 20.f) ? v : log1pf(expf(v));   // softplus, overflow-safe

    outM[i] = m;
    outS[i] = m + sqrtf(sp) * eps[i];
    outD[(size_t)i * NN + n] = sp;                 // diagonal over pre-zeroed std_mat
}

extern "C" void kernel_launch(void* const* d_in, const int* in_sizes, int n_in,
                              void* d_out, int out_size)
{
    const float* x   = (const float*)d_in[0];   // (2,128,512)
    const float* W   = (const float*)d_in[1];   // (1024,512)
    const float* b   = (const float*)d_in[2];   // (1024,)
    const float* eps = (const float*)d_in[3];   // (2,128,512)
    float* out = (float*)d_out;

    (void)in_sizes; (void)n_in; (void)out_size;

    // One-time resources, created on the first (correctness) call — before graph capture.
    static cudaStream_t s_side = nullptr;
    static cudaEvent_t  e_fork = nullptr;
    static cudaEvent_t  e_gemm = nullptr;
    if (s_side == nullptr) {
        cudaStreamCreateWithFlags(&s_side, cudaStreamNonBlocking);
        cudaEventCreateWithFlags(&e_fork, cudaEventDisableTiming);
        cudaEventCreateWithFlags(&e_gemm, cudaEventDisableTiming);
    }

    // Fork: side stream runs the split-K GEMM (touches only scratch, not std_mat)
    cudaEventRecord(e_fork, 0);
    cudaStreamWaitEvent(s_side, e_fork, 0);
    gemm_stage1<<<NTILES * KSPLIT, THREADS, 0, s_side>>>(x, W);
    cudaEventRecord(e_gemm, s_side);

    // Main stream: the memset node that measured 44us (6.1 TB/s) in R4 — keep it here.
    cudaMemsetAsync(out + 2 * SAMPLE_ELEMS, 0, STD_BYTES);

    // Join: combiner needs both the memset (stream order) and the GEMM (event)
    cudaStreamWaitEvent(0, e_gemm, 0);
    combine_stage2<<<SAMPLE_ELEMS / THREADS, THREADS>>>(b, eps, out);
}

// round 8
// speedup vs baseline: 2.0352x; 1.0166x over previous
#include <cuda_runtime.h>
#include <math.h>

// Problem constants
#define NN        512
#define ROWS      256
#define BM        32
#define BN        32
#define BK        32
#define NTILES    128          // (ROWS/BM)*(NN/BN)
#define KSPLIT    4
#define KCHUNK    128          // 512 / KSPLIT
#define THREADS   256

#define SAMPLE_ELEMS 131072
#define STD_BYTES    268435456ull        // 256*512*512 * 4B
#define STD_HALF     134217728ull        // half of it

// Split-K partial sums and softplus scratch
__device__ float g_pv[KSPLIT][ROWS][NN];
__device__ float g_pm[KSPLIT][ROWS][NN];
__device__ float g_sp[SAMPLE_ELEMS];

__global__ __launch_bounds__(THREADS)
void gemm_stage1(const float* __restrict__ x,
                 const float* __restrict__ W)
{
    __shared__ float Xs[BM][BK + 1];
    __shared__ float Wv[BN][BK + 1];
    __shared__ float Wm[BN][BK + 1];

    const int tile  = blockIdx.x & 127;
    const int chunk = blockIdx.x >> 7;
    const int bm    = tile >> 4;
    const int bn    = tile & 15;
    const int row0  = bm * BM;
    const int n0    = bn * BN;
    const int kbeg  = chunk * KCHUNK;

    const int tid = threadIdx.x;
    const int tx  = tid & 15;
    const int ty  = tid >> 4;
    const int rl  = ty * 2;
    const int nl  = tx * 2;

    const int lr = tid >> 3;
    const int lc = (tid & 7) * 4;

    float av[2][2] = {{0.f,0.f},{0.f,0.f}};
    float am[2][2] = {{0.f,0.f},{0.f,0.f}};

    for (int k0 = kbeg; k0 < kbeg + KCHUNK; k0 += BK) {
        float4 xv = *reinterpret_cast<const float4*>(&x[(size_t)(row0 + lr) * NN + k0 + lc]);
        Xs[lr][lc + 0] = xv.x; Xs[lr][lc + 1] = xv.y;
        Xs[lr][lc + 2] = xv.z; Xs[lr][lc + 3] = xv.w;

        float4 wv = *reinterpret_cast<const float4*>(&W[(size_t)(n0 + lr) * NN + k0 + lc]);
        Wv[lr][lc + 0] = wv.x; Wv[lr][lc + 1] = wv.y;
        Wv[lr][lc + 2] = wv.z; Wv[lr][lc + 3] = wv.w;

        float4 wm = *reinterpret_cast<const float4*>(&W[(size_t)(512 + n0 + lr) * NN + k0 + lc]);
        Wm[lr][lc + 0] = wm.x; Wm[lr][lc + 1] = wm.y;
        Wm[lr][lc + 2] = wm.z; Wm[lr][lc + 3] = wm.w;

        __syncthreads();

        #pragma unroll
        for (int kk = 0; kk < BK; kk++) {
            float x0 = Xs[rl][kk],     x1 = Xs[rl + 1][kk];
            float v0 = Wv[nl][kk],     v1 = Wv[nl + 1][kk];
            float m0 = Wm[nl][kk],     m1 = Wm[nl + 1][kk];
            av[0][0] += x0 * v0;  av[0][1] += x0 * v1;
            av[1][0] += x1 * v0;  av[1][1] += x1 * v1;
            am[0][0] += x0 * m0;  am[0][1] += x0 * m1;
            am[1][0] += x1 * m0;  am[1][1] += x1 * m1;
        }
        __syncthreads();
    }

    #pragma unroll
    for (int rr = 0; rr < 2; rr++) {
        #pragma unroll
        for (int nn = 0; nn < 2; nn++) {
            g_pv[chunk][row0 + rl + rr][n0 + nl + nn] = av[rr][nn];
            g_pm[chunk][row0 + rl + rr][n0 + nl + nn] = am[rr][nn];
        }
    }
}

// Combine partials -> sample, mu, and softplus scratch. Does NOT touch std_mat,
// so it runs concurrently with the memset fills.
__global__ __launch_bounds__(THREADS)
void combine_sm(const float* __restrict__ b,
                const float* __restrict__ eps,
                float* __restrict__ out)
{
    float* __restrict__ outS = out;
    float* __restrict__ outM = out + SAMPLE_ELEMS;

    const unsigned i = blockIdx.x * THREADS + threadIdx.x;
    const unsigned r = i >> 9;
    const unsigned n = i & 511u;

    float v = ((g_pv[0][r][n] + g_pv[1][r][n]) + (g_pv[2][r][n] + g_pv[3][r][n])) + b[n];
    float m = ((g_pm[0][r][n] + g_pm[1][r][n]) + (g_pm[2][r][n] + g_pm[3][r][n])) + b[512 + n];
    float sp = (v > 20.f) ? v : log1pf(expf(v));   // softplus, overflow-safe

    outM[i] = m;
    outS[i] = m + sqrtf(sp) * eps[i];
    g_sp[i] = sp;
}

// Scatter the softplus diagonal over the zeroed std_mat (the only post-join work)
__global__ __launch_bounds__(THREADS)
void diag_fixup(float* __restrict__ out)
{
    float* __restrict__ outD = out + 2 * SAMPLE_ELEMS;
    const unsigned i = blockIdx.x * THREADS + threadIdx.x;   // 0..131071
    outD[(size_t)i * NN + (i & 511u)] = g_sp[i];
}

extern "C" void kernel_launch(void* const* d_in, const int* in_sizes, int n_in,
                              void* d_out, int out_size)
{
    const float* x   = (const float*)d_in[0];
    const float* W   = (const float*)d_in[1];
    const float* b   = (const float*)d_in[2];
    const float* eps = (const float*)d_in[3];
    float* out = (float*)d_out;

    (void)in_sizes; (void)n_in; (void)out_size;

    // One-time resources, created on the first (correctness) call — before graph capture.
    static cudaStream_t s_cmp = nullptr;   // compute branch
    static cudaStream_t s_ms2 = nullptr;   // second memset branch
    static cudaEvent_t  e_fork = nullptr;
    static cudaEvent_t  e_cmp  = nullptr;
    static cudaEvent_t  e_ms2  = nullptr;
    if (s_cmp == nullptr) {
        cudaStreamCreateWithFlags(&s_cmp, cudaStreamNonBlocking);
        cudaStreamCreateWithFlags(&s_ms2, cudaStreamNonBlocking);
        cudaEventCreateWithFlags(&e_fork, cudaEventDisableTiming);
        cudaEventCreateWithFlags(&e_cmp,  cudaEventDisableTiming);
        cudaEventCreateWithFlags(&e_ms2,  cudaEventDisableTiming);
    }

    char* std_base = reinterpret_cast<char*>(out + 2 * SAMPLE_ELEMS);

    // Fork
    cudaEventRecord(e_fork, 0);
    cudaStreamWaitEvent(s_cmp, e_fork, 0);
    cudaStreamWaitEvent(s_ms2, e_fork, 0);

    // Compute branch: split-K GEMM then combine (sample, mu, softplus scratch)
    gemm_stage1<<<NTILES * KSPLIT, THREADS, 0, s_cmp>>>(x, W);
    combine_sm<<<SAMPLE_ELEMS / THREADS, THREADS, 0, s_cmp>>>(b, eps, out);
    cudaEventRecord(e_cmp, s_cmp);

    // Two concurrent memset halves: main stream + second branch
    cudaMemsetAsync(std_base + STD_HALF, 0, STD_BYTES - STD_HALF, s_ms2);
    cudaEventRecord(e_ms2, s_ms2);
    cudaMemsetAsync(std_base, 0, STD_HALF);

    // Join: diag scatter needs both memset halves and the combine
    cudaStreamWaitEvent(0, e_ms2, 0);
    cudaStreamWaitEvent(0, e_cmp, 0);
    diag_fixup<<<SAMPLE_ELEMS / THREADS, THREADS>>>(out);
}